// round 1
// baseline (speedup 1.0000x reference)
#include <cuda_runtime.h>
#include <math.h>

#define HIDDEN        1024
#define N_HEAD_WORDS  20000
#define N_HEAD        20003
#define N_TAIL1       40000
#define N_TAIL2       140000
#define E1            512
#define E2            256
#define OUT_STRIDE    200000
#define M_ROWS        1024

// ---- scratch (no allocations allowed; __device__ globals) ----
__device__ float g_proj1[M_ROWS * E1];     // 2 MB
__device__ float g_proj2[M_ROWS * E2];     // 1 MB
__device__ float g_cluster[M_ROWS * 4];    // cluster logits (use idx 0,1)
__device__ float g_sumexp1[M_ROWS];
__device__ float g_sumexp2[M_ROWS];

__global__ void zero_sums_kernel() {
    int i = blockIdx.x * blockDim.x + threadIdx.x;
    if (i < M_ROWS) { g_sumexp1[i] = 0.0f; g_sumexp2[i] = 0.0f; }
}

// ---------------------------------------------------------------------------
// Generic C[M,N] = A[M,K] * B[N,K]^T   (both row-major, inner-product over K)
// Tile: 128(M) x 64(N) x 16(K), 256 threads, 8x4 micro-tile per thread.
// MODE 0: plain store to C (ldc row stride, col offset = blockIdx.x*64)
// MODE 1: head -> n <  20000 goes to out[row*OUT_STRIDE + n]
//                 n >= 20000 goes to g_cluster[row*4 + (n-20000)]
// MODE 2: tail -> raw logits to C[row*OUT_STRIDE + n] (C pre-offset by caller)
//                 plus per-row sum(exp(logit)) accumulated into sumexp[]
// ---------------------------------------------------------------------------
template <int MODE>
__global__ __launch_bounds__(256)
void gemm128x64(const float* __restrict__ A, int lda,
                const float* __restrict__ B, int ldb,
                int N, int K,
                float* __restrict__ C, int ldc,
                float* __restrict__ sumexp)
{
    constexpr int BM = 128, BN = 64, BK = 16;
    __shared__ float As[BK][BM];
    __shared__ float Bs[BK][BN];
    __shared__ float rowsum[BM];

    const int bm  = blockIdx.y * BM;
    const int bn  = blockIdx.x * BN;
    const int tid = threadIdx.x;           // 0..255
    const int tm  = tid >> 4;              // 0..15 (row group of 8)
    const int tn  = tid & 15;              // 0..15 (col group of 4)

    // load assignments
    const int l_row = tid >> 2;            // 0..63
    const int l_k4  = (tid & 3) << 2;      // 0,4,8,12

    float acc[8][4];
    #pragma unroll
    for (int i = 0; i < 8; i++)
        #pragma unroll
        for (int j = 0; j < 4; j++) acc[i][j] = 0.0f;

    for (int k0 = 0; k0 < K; k0 += BK) {
        // A tile: 128 rows x 16 k  (M=1024 always -> no row bounds check)
        #pragma unroll
        for (int h = 0; h < 2; h++) {
            int row = l_row + 64 * h;
            float4 v = *(const float4*)&A[(size_t)(bm + row) * lda + k0 + l_k4];
            As[l_k4 + 0][row] = v.x;
            As[l_k4 + 1][row] = v.y;
            As[l_k4 + 2][row] = v.z;
            As[l_k4 + 3][row] = v.w;
        }
        // B tile: 64 rows x 16 k (bounds-checked on N)
        {
            int n = bn + l_row;
            float4 v = make_float4(0.f, 0.f, 0.f, 0.f);
            if (n < N) v = *(const float4*)&B[(size_t)n * ldb + k0 + l_k4];
            Bs[l_k4 + 0][l_row] = v.x;
            Bs[l_k4 + 1][l_row] = v.y;
            Bs[l_k4 + 2][l_row] = v.z;
            Bs[l_k4 + 3][l_row] = v.w;
        }
        __syncthreads();

        #pragma unroll
        for (int k = 0; k < BK; k++) {
            float a[8], b[4];
            #pragma unroll
            for (int i = 0; i < 8; i++) a[i] = As[k][tm * 8 + i];
            #pragma unroll
            for (int j = 0; j < 4; j++) b[j] = Bs[k][tn * 4 + j];
            #pragma unroll
            for (int i = 0; i < 8; i++)
                #pragma unroll
                for (int j = 0; j < 4; j++)
                    acc[i][j] += a[i] * b[j];
        }
        __syncthreads();
    }

    const int row0 = bm + tm * 8;
    const int col0 = bn + tn * 4;

    if (MODE == 0) {
        #pragma unroll
        for (int i = 0; i < 8; i++) {
            float4 v = make_float4(acc[i][0], acc[i][1], acc[i][2], acc[i][3]);
            *(float4*)&C[(size_t)(row0 + i) * ldc + col0] = v;
        }
    } else if (MODE == 1) {
        #pragma unroll
        for (int i = 0; i < 8; i++) {
            int r = row0 + i;
            #pragma unroll
            for (int j = 0; j < 4; j++) {
                int n = col0 + j;
                if (n < N_HEAD_WORDS) {
                    C[(size_t)r * OUT_STRIDE + n] = acc[i][j];
                } else if (n < N_HEAD) {
                    g_cluster[r * 4 + (n - N_HEAD_WORDS)] = acc[i][j];
                }
            }
        }
    } else { // MODE 2: tail
        float s[8];
        const bool full = (bn + BN) <= N;
        if (full) {
            #pragma unroll
            for (int i = 0; i < 8; i++) {
                int r = row0 + i;
                float4 v = make_float4(acc[i][0], acc[i][1], acc[i][2], acc[i][3]);
                *(float4*)&C[(size_t)r * OUT_STRIDE + col0] = v;
                s[i] = expf(acc[i][0]) + expf(acc[i][1]) +
                       expf(acc[i][2]) + expf(acc[i][3]);
            }
        } else {
            #pragma unroll
            for (int i = 0; i < 8; i++) {
                int r = row0 + i;
                s[i] = 0.0f;
                #pragma unroll
                for (int j = 0; j < 4; j++) {
                    int n = col0 + j;
                    if (n < N) {
                        C[(size_t)r * OUT_STRIDE + n] = acc[i][j];
                        s[i] += expf(acc[i][j]);
                    }
                }
            }
        }
        // reduce per-row sums across the 16 column-thread-groups
        if (tid < BM) rowsum[tid] = 0.0f;
        __syncthreads();
        #pragma unroll
        for (int i = 0; i < 8; i++)
            atomicAdd(&rowsum[tm * 8 + i], s[i]);
        __syncthreads();
        if (tid < BM) atomicAdd(&sumexp[bm + tid], rowsum[tid]);
    }
}

// out[row, col_off + c] += cluster[row][cl] - log(sumexp[row]),  c in [0, ncols)
__global__ void fixup_kernel(float* __restrict__ out,
                             const float* __restrict__ sumexp,
                             int col_off, int ncols, int cl)
{
    int row = blockIdx.y;
    float add = g_cluster[row * 4 + cl] - logf(sumexp[row]);
    int i = blockIdx.x * blockDim.x + threadIdx.x;   // float4 index
    if (i * 4 < ncols) {
        float4* p = (float4*)(out + (size_t)row * OUT_STRIDE + col_off);
        float4 v = p[i];
        v.x += add; v.y += add; v.z += add; v.w += add;
        p[i] = v;
    }
}

extern "C" void kernel_launch(void* const* d_in, const int* in_sizes, int n_in,
                              void* d_out, int out_size)
{
    const float* x       = (const float*)d_in[0];
    const float* W_head  = (const float*)d_in[1];
    const float* W_proj1 = (const float*)d_in[2];
    const float* W_tail1 = (const float*)d_in[3];
    const float* W_proj2 = (const float*)d_in[4];
    const float* W_tail2 = (const float*)d_in[5];
    float* out = (float*)d_out;

    float *proj1, *proj2, *se1, *se2;
    cudaGetSymbolAddress((void**)&proj1, g_proj1);
    cudaGetSymbolAddress((void**)&proj2, g_proj2);
    cudaGetSymbolAddress((void**)&se1,   g_sumexp1);
    cudaGetSymbolAddress((void**)&se2,   g_sumexp2);

    zero_sums_kernel<<<4, 256>>>();

    dim3 blk(256);
    // head: N=20003, K=1024
    gemm128x64<1><<<dim3((N_HEAD + 63) / 64, M_ROWS / 128), blk>>>(
        x, HIDDEN, W_head, HIDDEN, N_HEAD, HIDDEN, out, OUT_STRIDE, nullptr);
    // proj1: N=512, K=1024
    gemm128x64<0><<<dim3(E1 / 64, M_ROWS / 128), blk>>>(
        x, HIDDEN, W_proj1, HIDDEN, E1, HIDDEN, proj1, E1, nullptr);
    // proj2: N=256, K=1024
    gemm128x64<0><<<dim3(E2 / 64, M_ROWS / 128), blk>>>(
        x, HIDDEN, W_proj2, HIDDEN, E2, HIDDEN, proj2, E2, nullptr);
    // tail1: N=40000, K=512 -> raw logits into out[:,20000:60000] + sumexp1
    gemm128x64<2><<<dim3((N_TAIL1 + 63) / 64, M_ROWS / 128), blk>>>(
        proj1, E1, W_tail1, E1, N_TAIL1, E1, out + 20000, OUT_STRIDE, se1);
    // tail2: N=140000, K=256 -> raw logits into out[:,60000:200000] + sumexp2
    gemm128x64<2><<<dim3((N_TAIL2 + 63) / 64, M_ROWS / 128), blk>>>(
        proj2, E2, W_tail2, E2, N_TAIL2, E2, out + 60000, OUT_STRIDE, se2);

    // fixups: add cluster_logit - log(sumexp)
    fixup_kernel<<<dim3((N_TAIL1 / 4 + 255) / 256, M_ROWS), blk>>>(
        out, se1, 20000, N_TAIL1, 0);
    fixup_kernel<<<dim3((N_TAIL2 / 4 + 255) / 256, M_ROWS), blk>>>(
        out, se2, 60000, N_TAIL2, 1);
}

// round 3
// speedup vs baseline: 2.1480x; 2.1480x over previous
#include <cuda_runtime.h>
#include <math.h>
#include <stdint.h>

#define HIDDEN        1024
#define N_HEAD_WORDS  20000
#define N_HEAD        20003
#define N_TAIL1       40000
#define N_TAIL2       140000
#define E1            512
#define E2            256
#define OUT_STRIDE    200000
#define M_ROWS        1024

#define M_TILE 256
#define N_TILE 128
#define BK     32

#if defined(__CUDA_ARCH_FEAT_SM103_ALL) || defined(__CUDA_ARCH_FEAT_SM100_ALL)
#  define USE_TCGEN05 1
#else
#  define USE_TCGEN05 0
#endif

// ---- scratch (__device__ globals; no allocations allowed) ----
__device__ float g_proj1[M_ROWS * E1];
__device__ float g_proj2[M_ROWS * E2];
__device__ float g_cluster[M_ROWS * 4];
__device__ float g_sumexp1[M_ROWS];
__device__ float g_sumexp2[M_ROWS];

// ======================= common helpers =======================
static __device__ __forceinline__ uint32_t smem_u32(const void* p) {
    uint32_t a;
    asm("{ .reg .u64 t; cvta.to.shared.u64 t, %1; cvt.u32.u64 %0, t; }"
        : "=r"(a) : "l"(p));
    return a;
}

// tf32 round-to-nearest conversion (keeps fp32 container)
static __device__ __forceinline__ float to_tf32(float x) {
    uint32_t u;
    asm("cvt.rna.tf32.f32 %0, %1;" : "=r"(u) : "f"(x));
    return __uint_as_float(u);
}

// m16n8k8 tf32 mma.sync (baseline PTX, works on any sm_80+ target incl. sm_103)
static __device__ __forceinline__ void mma1688(float* d, const float* a, const float* b) {
    asm volatile(
        "mma.sync.aligned.m16n8k8.row.col.f32.tf32.tf32.f32 "
        "{%0,%1,%2,%3}, {%4,%5,%6,%7}, {%8,%9}, {%0,%1,%2,%3};"
        : "+f"(d[0]), "+f"(d[1]), "+f"(d[2]), "+f"(d[3])
        : "r"(__float_as_uint(a[0])), "r"(__float_as_uint(a[1])),
          "r"(__float_as_uint(a[2])), "r"(__float_as_uint(a[3])),
          "r"(__float_as_uint(b[0])), "r"(__float_as_uint(b[1])));
}

// ======================= tcgen05 helpers (only referenced when USE_TCGEN05) ===
static __device__ __forceinline__ uint32_t elect_one() {
    uint32_t p;
    asm volatile("{ .reg .pred p; elect.sync _|p, 0xFFFFFFFF; selp.b32 %0, 1, 0, p; }"
                 : "=r"(p));
    return p;
}
#define MBAR_INIT(a, c) \
    asm volatile("mbarrier.init.shared.b64 [%0], %1;" :: "r"(a), "r"(c) : "memory")
static __device__ __forceinline__ void mbar_wait(uint32_t mbar, uint32_t phase) {
    asm volatile(
        "{ .reg .pred P;\n"
        "WAITLOOP_%=:\n\t"
        "mbarrier.try_wait.parity.acquire.cta.shared::cta.b64 P, [%0], %1, 0x989680;\n\t"
        "@P bra.uni WAITDONE_%=;\n\t"
        "bra.uni WAITLOOP_%=;\n"
        "WAITDONE_%=:\n\t}"
        :: "r"(mbar), "r"(phase) : "memory");
}

#if USE_TCGEN05
#define TC_ALLOC(sa, n) \
    asm volatile("tcgen05.alloc.cta_group::1.sync.aligned.shared::cta.b32 [%0], %1;" \
                 :: "r"(sa), "r"(n) : "memory")
#define TC_RELINQ() \
    asm volatile("tcgen05.relinquish_alloc_permit.cta_group::1.sync.aligned;")
#define TC_DEALLOC(t, n) \
    asm volatile("tcgen05.dealloc.cta_group::1.sync.aligned.b32 %0, %1;" :: "r"(t), "r"(n))
#define TC_COMMIT(mb) \
    asm volatile("tcgen05.commit.cta_group::1.mbarrier::arrive::one.shared::cluster.b64 [%0];" \
                 :: "r"(mb) : "memory")
#define TC_FENCE_AFTER()  asm volatile("tcgen05.fence::after_thread_sync;" ::: "memory")
#define TC_FENCE_BEFORE() asm volatile("tcgen05.fence::before_thread_sync;" ::: "memory")
#define FENCE_ASYNC()     asm volatile("fence.proxy.async.shared::cta;" ::: "memory")
#define TC_WAIT_LD()      asm volatile("tcgen05.wait::ld.sync.aligned;" ::: "memory")
#define TC_LD_X32(r, addr) \
    asm volatile( \
        "tcgen05.ld.sync.aligned.32x32b.x32.b32 " \
        "{%0, %1, %2, %3, %4, %5, %6, %7, " \
        " %8, %9, %10, %11, %12, %13, %14, %15, " \
        " %16, %17, %18, %19, %20, %21, %22, %23, " \
        " %24, %25, %26, %27, %28, %29, %30, %31}, [%32];" \
        : "=r"((r)[0]),  "=r"((r)[1]),  "=r"((r)[2]),  "=r"((r)[3]), \
          "=r"((r)[4]),  "=r"((r)[5]),  "=r"((r)[6]),  "=r"((r)[7]), \
          "=r"((r)[8]),  "=r"((r)[9]),  "=r"((r)[10]), "=r"((r)[11]), \
          "=r"((r)[12]), "=r"((r)[13]), "=r"((r)[14]), "=r"((r)[15]), \
          "=r"((r)[16]), "=r"((r)[17]), "=r"((r)[18]), "=r"((r)[19]), \
          "=r"((r)[20]), "=r"((r)[21]), "=r"((r)[22]), "=r"((r)[23]), \
          "=r"((r)[24]), "=r"((r)[25]), "=r"((r)[26]), "=r"((r)[27]), \
          "=r"((r)[28]), "=r"((r)[29]), "=r"((r)[30]), "=r"((r)[31]) \
        : "r"(addr))

static __device__ __forceinline__ void mma_tf32(uint32_t d, uint64_t ad, uint64_t bd,
                                                uint32_t idesc, uint32_t en) {
    asm volatile(
        "{ .reg .pred p; setp.ne.u32 p, %4, 0;\n\t"
        "tcgen05.mma.cta_group::1.kind::tf32 [%0], %1, %2, %3, {%5, %5, %5, %5}, p; }\n"
        :: "r"(d), "l"(ad), "l"(bd), "r"(idesc), "r"(en), "r"(0u)
        : "memory");
}
static __device__ __forceinline__ uint64_t make_desc(uint32_t addr) {
    const uint64_t base = (uint64_t(2) << 61) | (uint64_t(1) << 46) |
                          (uint64_t(64) << 32) | (uint64_t(1) << 16);
    return base | ((uint64_t)(addr >> 4) & 0x3FFF);
}
#define IDESC_TF32 0x8200910u
#endif  // USE_TCGEN05

// SMEM layout: A buf0 @0 (32KB), A buf1 @32768, B buf0 @65536 (16KB), B buf1 @81920
#define TILE_SPAN   98304
#define SMEM_BYTES  (64 + 1024 + TILE_SPAN + 64)

__global__ void zero_sums_kernel() {
    int i = blockIdx.x * blockDim.x + threadIdx.x;
    if (i < M_ROWS) { g_sumexp1[i] = 0.0f; g_sumexp2[i] = 0.0f; }
}

// ---------------------------------------------------------------------------
// C[M,N] = A[M,K]*B[N,K]^T. Tile 256x128, BK=32, 256 threads.
// MODE 0: plain store; MODE 1: head split; MODE 2: tail store + sum(exp)
// ---------------------------------------------------------------------------
template <int MODE>
__global__ __launch_bounds__(256)
void tc_gemm(const float* __restrict__ A, int lda,
             const float* __restrict__ B, int ldb,
             int N, int K,
             float* __restrict__ C, long long ldc,
             float* __restrict__ sumexp)
{
    extern __shared__ char smem[];
    const uint32_t sbase = smem_u32(smem);
    const int tid = threadIdx.x;
    const uint32_t tiles_u32 = (sbase + 64 + 1023) & ~1023u;
    char* tiles = smem + (tiles_u32 - sbase);

    const int bm = blockIdx.x * M_TILE;
    const int bn = blockIdx.y * N_TILE;
    const int NC = K >> 5;

#if USE_TCGEN05
    // =================== tcgen05 tf32 path (sm_103a pass only) ===============
    const uint32_t tmem_ptr_a = sbase;
    const uint32_t mbar[2] = { sbase + 16, sbase + 24 };

    if (tid < 32) { TC_ALLOC(tmem_ptr_a, 256); TC_RELINQ(); }
    if (tid == 0) { MBAR_INIT(mbar[0], 1); MBAR_INIT(mbar[1], 1); }
    __syncthreads();
    uint32_t tmem;
    asm volatile("ld.shared.b32 %0, [%1];" : "=r"(tmem) : "r"(tmem_ptr_a));

    auto load_chunk = [&](int k0, int b) {
        char* Abuf = tiles + b * 32768;
        char* Bbuf = tiles + 65536 + b * 16384;
        #pragma unroll
        for (int j = 0; j < 8; j++) {
            int f = tid + 256 * j;
            int row = f >> 3, c16 = f & 7;
            float4 v = ((const float4*)(A + (size_t)(bm + row) * lda + k0))[c16];
            uint32_t byte = (uint32_t)(row << 7) + (c16 << 4);
            *(float4*)(Abuf + (byte ^ ((byte >> 3) & 0x70))) = v;
        }
        #pragma unroll
        for (int j = 0; j < 4; j++) {
            int f = tid + 256 * j;
            int row = f >> 3, c16 = f & 7;
            float4 v = make_float4(0.f, 0.f, 0.f, 0.f);
            if (bn + row < N)
                v = ((const float4*)(B + (size_t)(bn + row) * ldb + k0))[c16];
            uint32_t byte = (uint32_t)(row << 7) + (c16 << 4);
            *(float4*)(Bbuf + (byte ^ ((byte >> 3) & 0x70))) = v;
        }
        FENCE_ASYNC();
    };

    load_chunk(0, 0);
    __syncthreads();

    uint32_t ph[2] = { 0, 0 };
    for (int c = 0; c < NC; c++) {
        const int cur = c & 1;
        if (tid < 32) {
            uint64_t ad0 = make_desc(tiles_u32 + cur * 32768);
            uint64_t ad1 = make_desc(tiles_u32 + cur * 32768 + 16384);
            uint64_t bd  = make_desc(tiles_u32 + 65536 + cur * 16384);
            if (elect_one()) {
                #pragma unroll
                for (int ks = 0; ks < 4; ks++) {
                    uint32_t en = (c > 0 || ks > 0) ? 1u : 0u;
                    mma_tf32(tmem,       ad0 + ks * 2, bd + ks * 2, IDESC_TF32, en);
                    mma_tf32(tmem + 128, ad1 + ks * 2, bd + ks * 2, IDESC_TF32, en);
                }
                TC_COMMIT(mbar[cur]);
            }
        }
        if (c + 1 < NC) {
            const int nxt = cur ^ 1;
            if (c >= 1) { mbar_wait(mbar[nxt], ph[nxt]); ph[nxt] ^= 1; }
            load_chunk((c + 1) << 5, nxt);
        }
        __syncthreads();
    }
    { const int last = (NC - 1) & 1; mbar_wait(mbar[last], ph[last]); }
    TC_FENCE_AFTER();

    const int h = tid >> 7;
    const int sp = (tid >> 5) & 3;
    const int lane = tid & 31;
    const int row = bm + h * 128 + sp * 32 + lane;
    const uint32_t dbase = tmem + h * 128;

    float ssum = 0.0f;
    #pragma unroll
    for (int q = 0; q < 4; q++) {
        uint32_t r[32];
        TC_LD_X32(r, dbase + q * 32);
        TC_WAIT_LD();
        const int cb = q * 32;
        if (MODE == 0) {
            #pragma unroll
            for (int v = 0; v < 8; v++)
                *(float4*)&C[(size_t)row * ldc + bn + cb + v * 4] =
                    make_float4(__uint_as_float(r[v*4+0]), __uint_as_float(r[v*4+1]),
                                __uint_as_float(r[v*4+2]), __uint_as_float(r[v*4+3]));
        } else if (MODE == 1) {
            if (bn + N_TILE <= N_HEAD_WORDS) {
                #pragma unroll
                for (int v = 0; v < 8; v++)
                    *(float4*)&C[(size_t)row * ldc + bn + cb + v * 4] =
                        make_float4(__uint_as_float(r[v*4+0]), __uint_as_float(r[v*4+1]),
                                    __uint_as_float(r[v*4+2]), __uint_as_float(r[v*4+3]));
            } else {
                #pragma unroll
                for (int v = 0; v < 32; v++) {
                    int n = bn + cb + v;
                    float val = __uint_as_float(r[v]);
                    if (n < N_HEAD_WORDS)  C[(size_t)row * ldc + n] = val;
                    else if (n < N_HEAD)   g_cluster[row * 4 + (n - N_HEAD_WORDS)] = val;
                }
            }
        } else {
            if (bn + N_TILE <= N) {
                #pragma unroll
                for (int v = 0; v < 8; v++) {
                    float a0 = __uint_as_float(r[v*4+0]), a1 = __uint_as_float(r[v*4+1]);
                    float a2 = __uint_as_float(r[v*4+2]), a3 = __uint_as_float(r[v*4+3]);
                    *(float4*)&C[(size_t)row * ldc + bn + cb + v * 4] =
                        make_float4(a0, a1, a2, a3);
                    ssum += __expf(a0) + __expf(a1) + __expf(a2) + __expf(a3);
                }
            } else {
                #pragma unroll
                for (int v = 0; v < 32; v++) {
                    int n = bn + cb + v;
                    if (n < N) {
                        float val = __uint_as_float(r[v]);
                        C[(size_t)row * ldc + n] = val;
                        ssum += __expf(val);
                    }
                }
            }
        }
    }
    if (MODE == 2) atomicAdd(&sumexp[row], ssum);

    TC_FENCE_BEFORE();
    __syncthreads();
    if (tid < 32) TC_DEALLOC(tmem, 256);

#else
    // =================== mma.sync tf32 fallback (plain sm_103) ===============
    const int warp = tid >> 5, lane = tid & 31;
    const int wm = warp & 3;            // 4 M warp-groups (64 rows each)
    const int wn = warp >> 2;           // 2 N warp-groups (64 cols each)
    const int g = lane >> 2, tig = lane & 3;

    float acc[4][8][4];
    #pragma unroll
    for (int mt = 0; mt < 4; mt++)
        #pragma unroll
        for (int nt = 0; nt < 8; nt++)
            #pragma unroll
            for (int i = 0; i < 4; i++) acc[mt][nt][i] = 0.0f;

    float4 pa[8], pb[4];
    auto ldg_chunk = [&](int k0) {
        #pragma unroll
        for (int j = 0; j < 8; j++) {
            int f = tid + 256 * j;
            int row = f >> 3, c16 = f & 7;
            pa[j] = ((const float4*)(A + (size_t)(bm + row) * lda + k0))[c16];
        }
        #pragma unroll
        for (int j = 0; j < 4; j++) {
            int f = tid + 256 * j;
            int row = f >> 3, c16 = f & 7;
            pb[j] = make_float4(0.f, 0.f, 0.f, 0.f);
            if (bn + row < N)
                pb[j] = ((const float4*)(B + (size_t)(bn + row) * ldb + k0))[c16];
        }
    };
    auto sts_chunk = [&](int b) {
        char* Abuf = tiles + b * 32768;
        char* Bbuf = tiles + 65536 + b * 16384;
        #pragma unroll
        for (int j = 0; j < 8; j++) {
            int f = tid + 256 * j;
            int row = f >> 3, c16 = f & 7;
            uint32_t byte = (uint32_t)(row << 7) + (c16 << 4);
            *(float4*)(Abuf + (byte ^ ((byte >> 3) & 0x70))) = pa[j];
        }
        #pragma unroll
        for (int j = 0; j < 4; j++) {
            int f = tid + 256 * j;
            int row = f >> 3, c16 = f & 7;
            uint32_t byte = (uint32_t)(row << 7) + (c16 << 4);
            *(float4*)(Bbuf + (byte ^ ((byte >> 3) & 0x70))) = pb[j];
        }
    };
    auto ldS = [&](const char* base, int row, int col) -> float {
        uint32_t byte = ((uint32_t)row << 7) + ((uint32_t)col << 2);
        return *(const float*)(base + (byte ^ ((byte >> 3) & 0x70)));
    };
    auto compute_chunk = [&](int b) {
        const char* Abuf = tiles + b * 32768;
        const char* Bbuf = tiles + 65536 + b * 16384;
        #pragma unroll
        for (int ks = 0; ks < 4; ks++) {
            float bf[8][2];
            #pragma unroll
            for (int nt = 0; nt < 8; nt++) {
                int n = wn * 64 + nt * 8 + g;
                bf[nt][0] = to_tf32(ldS(Bbuf, n, ks * 8 + tig));
                bf[nt][1] = to_tf32(ldS(Bbuf, n, ks * 8 + tig + 4));
            }
            #pragma unroll
            for (int mt = 0; mt < 4; mt++) {
                int r0 = wm * 64 + mt * 16;
                float af[4];
                af[0] = to_tf32(ldS(Abuf, r0 + g,     ks * 8 + tig));
                af[1] = to_tf32(ldS(Abuf, r0 + g + 8, ks * 8 + tig));
                af[2] = to_tf32(ldS(Abuf, r0 + g,     ks * 8 + tig + 4));
                af[3] = to_tf32(ldS(Abuf, r0 + g + 8, ks * 8 + tig + 4));
                #pragma unroll
                for (int nt = 0; nt < 8; nt++)
                    mma1688(acc[mt][nt], af, bf[nt]);
            }
        }
    };

    ldg_chunk(0);
    sts_chunk(0);
    __syncthreads();
    for (int c = 0; c < NC; c++) {
        const int cur = c & 1;
        if (c + 1 < NC) ldg_chunk((c + 1) << 5);
        compute_chunk(cur);
        if (c + 1 < NC) {
            sts_chunk(cur ^ 1);
            __syncthreads();
        }
    }

    // ---- epilogue ----
    const bool fullw = (bn + N_TILE <= N_HEAD_WORDS);
    const bool fullN = (bn + N_TILE <= N);
    float rs[4][2];
    #pragma unroll
    for (int mt = 0; mt < 4; mt++) { rs[mt][0] = 0.f; rs[mt][1] = 0.f; }

    #pragma unroll
    for (int mt = 0; mt < 4; mt++) {
        const int r = bm + wm * 64 + mt * 16 + g;
        #pragma unroll
        for (int nt = 0; nt < 8; nt++) {
            float* d = acc[mt][nt];
            const int cc = bn + wn * 64 + nt * 8 + 2 * tig;
            if (MODE == 0) {
                *(float2*)&C[(size_t)r * ldc + cc]       = make_float2(d[0], d[1]);
                *(float2*)&C[(size_t)(r + 8) * ldc + cc] = make_float2(d[2], d[3]);
            } else if (MODE == 1) {
                if (fullw) {
                    *(float2*)&C[(size_t)r * ldc + cc]       = make_float2(d[0], d[1]);
                    *(float2*)&C[(size_t)(r + 8) * ldc + cc] = make_float2(d[2], d[3]);
                } else {
                    #pragma unroll
                    for (int i = 0; i < 4; i++) {
                        int rr = r + (i >> 1) * 8;
                        int n  = cc + (i & 1);
                        float val = d[i];
                        if (n < N_HEAD_WORDS)  C[(size_t)rr * ldc + n] = val;
                        else if (n < N_HEAD)   g_cluster[rr * 4 + (n - N_HEAD_WORDS)] = val;
                    }
                }
            } else {
                if (fullN) {
                    *(float2*)&C[(size_t)r * ldc + cc]       = make_float2(d[0], d[1]);
                    *(float2*)&C[(size_t)(r + 8) * ldc + cc] = make_float2(d[2], d[3]);
                    rs[mt][0] += __expf(d[0]) + __expf(d[1]);
                    rs[mt][1] += __expf(d[2]) + __expf(d[3]);
                } else {
                    #pragma unroll
                    for (int i = 0; i < 4; i++) {
                        int rr = r + (i >> 1) * 8;
                        int n  = cc + (i & 1);
                        if (n < N) {
                            C[(size_t)rr * ldc + n] = d[i];
                            rs[mt][i >> 1] += __expf(d[i]);
                        }
                    }
                }
            }
        }
    }
    if (MODE == 2) {
        __syncthreads();
        float* rowsum = (float*)tiles;
        rowsum[tid] = 0.0f;
        __syncthreads();
        #pragma unroll
        for (int mt = 0; mt < 4; mt++) {
            atomicAdd(&rowsum[wm * 64 + mt * 16 + g],     rs[mt][0]);
            atomicAdd(&rowsum[wm * 64 + mt * 16 + g + 8], rs[mt][1]);
        }
        __syncthreads();
        atomicAdd(&sumexp[bm + tid], rowsum[tid]);
    }
#endif
}

// out[row, col_off + c] += cluster[row][cl] - log(sumexp[row])
__global__ void fixup_kernel(float* __restrict__ out,
                             const float* __restrict__ sumexp,
                             int col_off, int ncols, int cl)
{
    int row = blockIdx.y;
    float add = g_cluster[row * 4 + cl] - logf(sumexp[row]);
    int i = blockIdx.x * blockDim.x + threadIdx.x;
    if (i * 4 < ncols) {
        float4* p = (float4*)(out + (size_t)row * OUT_STRIDE + col_off);
        float4 v = p[i];
        v.x += add; v.y += add; v.z += add; v.w += add;
        p[i] = v;
    }
}

extern "C" void kernel_launch(void* const* d_in, const int* in_sizes, int n_in,
                              void* d_out, int out_size)
{
    const float* x       = (const float*)d_in[0];
    const float* W_head  = (const float*)d_in[1];
    const float* W_proj1 = (const float*)d_in[2];
    const float* W_tail1 = (const float*)d_in[3];
    const float* W_proj2 = (const float*)d_in[4];
    const float* W_tail2 = (const float*)d_in[5];
    float* out = (float*)d_out;

    float *proj1, *proj2, *se1, *se2;
    cudaGetSymbolAddress((void**)&proj1, g_proj1);
    cudaGetSymbolAddress((void**)&proj2, g_proj2);
    cudaGetSymbolAddress((void**)&se1,   g_sumexp1);
    cudaGetSymbolAddress((void**)&se2,   g_sumexp2);

    cudaFuncSetAttribute(tc_gemm<0>, cudaFuncAttributeMaxDynamicSharedMemorySize, SMEM_BYTES);
    cudaFuncSetAttribute(tc_gemm<1>, cudaFuncAttributeMaxDynamicSharedMemorySize, SMEM_BYTES);
    cudaFuncSetAttribute(tc_gemm<2>, cudaFuncAttributeMaxDynamicSharedMemorySize, SMEM_BYTES);

    zero_sums_kernel<<<4, 256>>>();

    tc_gemm<1><<<dim3(4, (N_HEAD  + 127) / 128), 256, SMEM_BYTES>>>(
        x, HIDDEN, W_head, HIDDEN, N_HEAD, HIDDEN, out, OUT_STRIDE, nullptr);
    tc_gemm<0><<<dim3(4, E1 / 128), 256, SMEM_BYTES>>>(
        x, HIDDEN, W_proj1, HIDDEN, E1, HIDDEN, proj1, E1, nullptr);
    tc_gemm<0><<<dim3(4, E2 / 128), 256, SMEM_BYTES>>>(
        x, HIDDEN, W_proj2, HIDDEN, E2, HIDDEN, proj2, E2, nullptr);
    tc_gemm<2><<<dim3(4, (N_TAIL1 + 127) / 128), 256, SMEM_BYTES>>>(
        proj1, E1, W_tail1, E1, N_TAIL1, E1, out + 20000, OUT_STRIDE, se1);
    tc_gemm<2><<<dim3(4, (N_TAIL2 + 127) / 128), 256, SMEM_BYTES>>>(
        proj2, E2, W_tail2, E2, N_TAIL2, E2, out + 60000, OUT_STRIDE, se2);

    fixup_kernel<<<dim3((N_TAIL1 / 4 + 255) / 256, M_ROWS), 256>>>(
        out, se1, 20000, N_TAIL1, 0);
    fixup_kernel<<<dim3((N_TAIL2 / 4 + 255) / 256, M_ROWS), 256>>>(
        out, se2, 60000, N_TAIL2, 1);
}